// round 10
// baseline (speedup 1.0000x reference)
#include <cuda_runtime.h>
#include <cstdint>
#include <cstddef>

#define WIDTH  2048
#define DEPTH  8
#define DP1    9
#define TMOD   242          // 30*DEPTH + 2
#define WD     16384        // WIDTH*DEPTH
#define RPB    8            // rows per wphase block
#define WBLK   (WIDTH / RPB)   // 256 blocks, also # of hidden partials

// d_out layout (float32, reference return order)
#define OFF_OUT   0ULL
#define OFF_STATE 1ULL
#define OFF_SA    18433ULL
#define OFF_SG    4478977ULL
#define OFF_OG    4495361ULL
#define OFF_GRAD  8955905ULL
#define OFF_OWG   42510337ULL

#define N_SAOG    (WIDTH * DP1 * TMOD)     // 4460544
#define NQ_SAOG   1115135                  // quads idx = 3+4q
#define SAOG_BLK  ((NQ_SAOG + 255) / 256)  // 4356
#define NQ_GROW   4095                     // per-row quads k = 3+4q

// scratch (allocation-free)
__device__ float g_hpart[WBLK][WD];       // hidden partials (16 MB)
__device__ float g_contrib[WD];           // contrib[i*8+a], a=0..6
__device__ float g_m[WD];
__device__ float g_mshift[WD];            // g_mshift[t] = m[t+3]
__device__ float g_aprev[WD];
__device__ float g_out_acc;

__device__ __forceinline__ int posmod(int v, int m) {
    int r = v % m;
    return r < 0 ? r + m : r;
}

// ---------------------------------------------------------------------------
// W-phase: ONE row-major pass over W computing BOTH reductions.
// Block owns 8 rows. Thread owns 64 fixed k (16 float4 quads, q = tid+s*256):
//   hidden[k]   partial accumulated in registers across the 8 rows
//   contrib row-dot reduced per row via parity-preserving shfl
// q parity == tid parity -> thread's d-range fixed: dbase = (tid&1)*4.
// ---------------------------------------------------------------------------
__global__ void __launch_bounds__(256, 2)
k_wphase(const float* __restrict__ W,
         const float* __restrict__ state_in,
         const float* __restrict__ sgrad) {
    __shared__ float ss[RPB][8];           // state rows
    __shared__ float csm[RPB][16][4];      // per-warp contrib partials

    const int tid = threadIdx.x;
    const int i0  = blockIdx.x * RPB;
    const int wid = tid >> 5, lane = tid & 31;
    const int par = tid & 1;
    const int dbase = par * 4;

    if (blockIdx.x == 0 && tid == 0) g_out_acc = 0.f;

    if (tid < RPB * 8) {
        int r = tid >> 3, d = tid & 7;
        ss[r][d] = state_in[(size_t)(i0 + r) * DP1 + d];
    }
    __syncthreads();

    float4 hacc[16];
#pragma unroll
    for (int s = 0; s < 16; ++s) hacc[s] = make_float4(0.f, 0.f, 0.f, 0.f);

    const float4* sg4 = reinterpret_cast<const float4*>(sgrad);

    for (int r = 0; r < RPB; ++r) {
        const float4* Wr = reinterpret_cast<const float4*>(W + (size_t)(i0 + r) * WD);
        const float4 sv = *reinterpret_cast<const float4*>(&ss[r][dbase]);
        float4 cacc = make_float4(0.f, 0.f, 0.f, 0.f);

#pragma unroll
        for (int s = 0; s < 16; ++s) {
            const int q = tid + s * 256;
            float4 w4 = Wr[q];
            float4 g4 = sg4[q];            // 64 KB, L1-hot after row 0
            if (par == 0) g4.x = 0.f;      // d==0 excluded from contrib
            hacc[s].x = fmaf(w4.x, sv.x, hacc[s].x);
            hacc[s].y = fmaf(w4.y, sv.y, hacc[s].y);
            hacc[s].z = fmaf(w4.z, sv.z, hacc[s].z);
            hacc[s].w = fmaf(w4.w, sv.w, hacc[s].w);
            cacc.x = fmaf(w4.x, g4.x, cacc.x);
            cacc.y = fmaf(w4.y, g4.y, cacc.y);
            cacc.z = fmaf(w4.z, g4.z, cacc.z);
            cacc.w = fmaf(w4.w, g4.w, cacc.w);
        }
        // parity-preserving warp reduction: lane0 = even-lane sum (d 0-3),
        // lane1 = odd-lane sum (d 4-7)
#pragma unroll
        for (int dist = 2; dist <= 16; dist <<= 1) {
            cacc.x += __shfl_xor_sync(0xffffffffu, cacc.x, dist);
            cacc.y += __shfl_xor_sync(0xffffffffu, cacc.y, dist);
            cacc.z += __shfl_xor_sync(0xffffffffu, cacc.z, dist);
            cacc.w += __shfl_xor_sync(0xffffffffu, cacc.w, dist);
        }
        if (lane < 2)
            *reinterpret_cast<float4*>(&csm[r][wid * 2 + lane][0]) = cacc;
    }

    // hidden partials out (coalesced float4)
    float4* hp = reinterpret_cast<float4*>(g_hpart[blockIdx.x]);
#pragma unroll
    for (int s = 0; s < 16; ++s) hp[tid + s * 256] = hacc[s];

    __syncthreads();
    // contrib: sum 8 warps per (row, d); store at slot a = d-1
    if (tid < RPB * 8) {
        int r = tid >> 3, d = tid & 7;
        if (d >= 1) {
            float sum = 0.f;
#pragma unroll
            for (int w = 0; w < 8; ++w) sum += csm[r][w * 2 + (d >> 2)][d & 3];
            g_contrib[(size_t)(i0 + r) * 8 + d - 1] = sum;
        }
    }
}

// ---------------------------------------------------------------------------
// finalize — state/owg, output dot, full sg logic, m / m-shift / aprev.
// tia(a) = time + 2a - 14 (mod 242); tia==time only at a=7, (tia±1)!=time
// for all a -> all sa/og reads at a<7 hit the ORIGINAL arrays; at a=7 the
// only aliased read is this thread's own fresh state value.
// ---------------------------------------------------------------------------
__global__ void k_finalize(float* __restrict__ out,
                           const float* __restrict__ x,
                           const float* __restrict__ ow,
                           const float* __restrict__ sa_in,
                           const float* __restrict__ og_in,
                           const int* __restrict__ time_p) {
    const int k = blockIdx.x * blockDim.x + threadIdx.x;   // 0..WD-1
    const int w = k >> 3, a = k & 7;

    float h = 0.f;
#pragma unroll 8
    for (int c = 0; c < WBLK; ++c) h += g_hpart[c][k];
    float s = fmaxf(h, 0.f);

    size_t o = (size_t)w * DP1 + a + 1;
    out[OFF_STATE + o] = s;
    out[OFF_OWG + o]   = s;
    float v = ow[o] * s;
    if (a == 0) {
        float xv = x[w];
        out[OFF_STATE + (size_t)w * DP1] = xv;
        out[OFF_OWG   + (size_t)w * DP1] = xv;
        v = fmaf(ow[(size_t)w * DP1], xv, v);
    }

    const int time = *time_p;
    const int tia = posmod(time - 2 * DEPTH + 2 * (a + 1), TMOD);
    float sgv, rg, aprev;
    if (a < DEPTH - 1) {
        int t1 = (tia + 1) % TMOD;
        float rmv = sa_in[((size_t)w * DP1 + a + 2) * TMOD + t1];
        sgv = fmaf(rmv > 0.f ? 1.f : 0.f, g_contrib[k],
                   og_in[((size_t)w * DP1 + a + 1) * TMOD + tia]);
        rg = (sa_in[((size_t)w * DP1 + a + 1) * TMOD + tia] > 0.f) ? 1.f : 0.f;
        aprev = sa_in[((size_t)w * DP1 + a) * TMOD + posmod(tia - 1, TMOD)];
    } else {
        sgv = ow[(size_t)w * DP1 + DEPTH];
        rg = (s > 0.f) ? 1.f : 0.f;
        aprev = sa_in[((size_t)w * DP1 + DEPTH - 1) * TMOD + posmod(time - 1, TMOD)];
    }
    out[OFF_SG + k] = sgv;
    float mval = sgv * rg;
    g_m[k] = mval;
    if (k >= 3) g_mshift[k - 3] = mval;
    g_aprev[k] = aprev;

    __shared__ float red[8];
#pragma unroll
    for (int off = 16; off; off >>= 1)
        v += __shfl_down_sync(0xffffffffu, v, off);
    if ((threadIdx.x & 31) == 0) red[threadIdx.x >> 5] = v;
    __syncthreads();
    if (threadIdx.x == 0) {
        float t = 0.f;
#pragma unroll
        for (int i = 0; i < 8; ++i) t += red[i];
        atomicAdd(&g_out_acc, t);
    }
}

// ---------------------------------------------------------------------------
// Post-phase (exact round-8 version, measured best): bx < SAOG_BLK -> saog
// quad block; else grad row i = bx - SAOG_BLK (block-per-row, mshift).
// ---------------------------------------------------------------------------
__global__ void k_post(float* __restrict__ out,
                       const float* __restrict__ sa_in,
                       const float* __restrict__ og_in,
                       const float* __restrict__ ow,
                       const int* __restrict__ time_p) {
    const int tid = threadIdx.x;
    const int bx  = blockIdx.x;

    if (bx < SAOG_BLK) {
        const int time = *time_p;
        const int q = bx * 256 + tid;
        if (q >= NQ_SAOG) return;
        const int idx = 3 + 4 * q;

        const float4* sa4 = reinterpret_cast<const float4*>(sa_in);
        const float4* og4 = reinterpret_cast<const float4*>(og_in);
        float4 sA = sa4[q], sB = sa4[q + 1];
        float4 oA = og4[q], oB = og4[q + 1];
        float sv[4] = {sA.w, sB.x, sB.y, sB.z};
        float ov[4] = {oA.w, oB.x, oB.y, oB.z};

        int t  = idx % TMOD;
        int wc = idx / TMOD;
#pragma unroll
        for (int e = 0; e < 4; ++e) {
            int tt = t + e, wcc = wc;
            if (tt >= TMOD) { tt -= TMOD; ++wcc; }
            if (tt == time) {
                sv[e] = out[OFF_STATE + wcc];
                ov[e] = ow[wcc];
            }
        }
        *reinterpret_cast<float4*>(&out[OFF_SA + idx]) =
            make_float4(sv[0], sv[1], sv[2], sv[3]);
        *reinterpret_cast<float4*>(&out[OFF_OG + idx]) =
            make_float4(ov[0], ov[1], ov[2], ov[3]);

        if (q == 0) {
#pragma unroll
            for (int e = 0; e < 3; ++e) {
                out[OFF_SA + e] = (e == time) ? out[OFF_STATE] : sa_in[e];
                out[OFF_OG + e] = (e == time) ? ow[0] : og_in[e];
            }
        }
        if (q == NQ_SAOG - 1) {
            const int it = N_SAOG - 1;
            int tt = it % TMOD, wcc = it / TMOD;
            out[OFF_SA + it] = (tt == time) ? out[OFF_STATE + wcc] : sa_in[it];
            out[OFF_OG + it] = (tt == time) ? ow[wcc] : og_in[it];
        }
    } else {
        const int i = bx - SAOG_BLK;
        if (i == 0 && tid == 0) out[OFF_OUT] = g_out_acc;

        const float* ap = g_aprev + (size_t)i * 8;
        const float4 apv = (tid & 1)
            ? make_float4(__ldg(ap + 7), __ldg(ap + 0), __ldg(ap + 1), __ldg(ap + 2))
            : make_float4(__ldg(ap + 3), __ldg(ap + 4), __ldg(ap + 5), __ldg(ap + 6));

        float* dst = out + OFF_GRAD + (size_t)i * WD;
        const float4* ms4 = reinterpret_cast<const float4*>(g_mshift);

        for (int q = tid; q < NQ_GROW; q += 256) {
            float4 mv = ms4[q];
            *reinterpret_cast<float4*>(dst + 3 + 4 * q) =
                make_float4(apv.x * mv.x, apv.y * mv.y,
                            apv.z * mv.z, apv.w * mv.w);
        }
        if (tid == 0) {
            dst[0] = __ldg(ap + 0) * g_m[0];
            dst[1] = __ldg(ap + 1) * g_m[1];
            dst[2] = __ldg(ap + 2) * g_m[2];
        } else if (tid == 1) {
            dst[WD - 1] = __ldg(ap + 7) * g_m[WD - 1];
        }
    }
}

// ---------------------------------------------------------------------------
extern "C" void kernel_launch(void* const* d_in, const int* in_sizes, int n_in,
                              void* d_out, int out_size) {
    const float* x    = (const float*)d_in[0];
    const float* W    = (const float*)d_in[1];
    const float* ow   = (const float*)d_in[2];
    const float* st   = (const float*)d_in[3];
    const float* sa   = (const float*)d_in[4];
    const float* sgr  = (const float*)d_in[5];
    const float* og   = (const float*)d_in[6];
    const int*   tim  = (const int*)d_in[7];
    float* out = (float*)d_out;

    k_wphase<<<WBLK, 256>>>(W, st, sgr);
    k_finalize<<<WD / 256, 256>>>(out, x, ow, sa, og, tim);
    k_post<<<SAOG_BLK + WIDTH, 256>>>(out, sa, og, ow, tim);
}

// round 11
// speedup vs baseline: 1.4114x; 1.4114x over previous
#include <cuda_runtime.h>
#include <cstdint>
#include <cstddef>

#define WIDTH  2048
#define DEPTH  8
#define DP1    9
#define TMOD   242          // 30*DEPTH + 2
#define WD     16384        // WIDTH*DEPTH
#define NSPLIT 16           // i-splits for hidden
#define CHUNK  128          // WIDTH / NSPLIT
#define HBLK   256          // hidden blocks (16 kblk x 16 split)
#define WROLE  (HBLK + WIDTH)       // 2304 W-role blocks
#define MAIN_BLK (WROLE * 3)        // 6912: bx%3==0 -> W-role, else saog

// d_out layout (float32, reference return order)
#define OFF_OUT   0ULL
#define OFF_STATE 1ULL
#define OFF_SA    18433ULL
#define OFF_SG    4478977ULL
#define OFF_OG    4495361ULL
#define OFF_GRAD  8955905ULL
#define OFF_OWG   42510337ULL

#define N_SAOG    (WIDTH * DP1 * TMOD)     // 4460544
#define NQ_SAOG   1115135                  // quads idx = 3+4q
#define NQ_GROW   4095                     // per-row quads k = 3+4q

// scratch (allocation-free)
__device__ float g_hpart[NSPLIT][WD];     // hidden partials (1 MB)
__device__ float g_contrib[WD];           // contrib[i*8+a], a=0..6
__device__ float g_m[WD];
__device__ float g_mshift[WD];            // g_mshift[t] = m[t+3]
__device__ float g_aprev[WD];
__device__ float g_out_acc;

__device__ __forceinline__ int posmod(int v, int m) {
    int r = v % m;
    return r < 0 ? r + m : r;
}

// ---------------------------------------------------------------------------
// MAIN: three roles in one grid so the pure-stream saog copy fills DRAM slots
// the W reductions leave idle. bx%3==0 -> W-role (round-8 ordering preserved:
// id<256 hidden, else contrib row); bx%3!=0 -> saog quad copy (NO time logic;
// finalize overwrites the time slice afterwards).
// ---------------------------------------------------------------------------
__global__ void k_main(const float* __restrict__ W,
                       const float* __restrict__ state_in,
                       const float* __restrict__ sgrad,
                       float* __restrict__ out,
                       const float* __restrict__ sa_in,
                       const float* __restrict__ og_in) {
    __shared__ float sh[CHUNK * 8];
    const int tid = threadIdx.x;
    const int bx  = blockIdx.x;

    if (bx % 3 == 0) {
        const int wr = bx / 3;             // 0..2303, round-8 relative order
        if (wr == 0 && tid == 0) g_out_acc = 0.f;

        if (wr < HBLK) {
            // ---- hidden partial: hidden[k] = sum_i W[i*WD+k]*state[i,k&7]
            const int kblk  = wr & 15;
            const int split = wr >> 4;
            const int k4 = kblk * 1024 + tid * 4;
            const int i0 = split * CHUNK;
            const int dbase = (tid & 1) * 4;

            for (int idx = tid; idx < CHUNK * 8; idx += 256) {
                int i = idx >> 3, d = idx & 7;
                sh[idx] = state_in[(size_t)(i0 + i) * DP1 + d];
            }
            __syncthreads();

            const float* Wp = W + (size_t)i0 * WD + k4;
            float4 acc = make_float4(0.f, 0.f, 0.f, 0.f);
#pragma unroll 8
            for (int i = 0; i < CHUNK; ++i) {
                float4 w4 = *reinterpret_cast<const float4*>(Wp + (size_t)i * WD);
                float4 sv = *reinterpret_cast<const float4*>(&sh[i * 8 + dbase]);
                acc.x = fmaf(w4.x, sv.x, acc.x);
                acc.y = fmaf(w4.y, sv.y, acc.y);
                acc.z = fmaf(w4.z, sv.z, acc.z);
                acc.w = fmaf(w4.w, sv.w, acc.w);
            }
            *reinterpret_cast<float4*>(&g_hpart[split][k4]) = acc;
        } else {
            // ---- contrib[i,a] = sum_j W[i,j,a+1]*sgrad[j,a+1], a=0..6
            const int i = wr - HBLK;
            const float4* Wr = reinterpret_cast<const float4*>(W + (size_t)i * WD);
            const float4* gg = reinterpret_cast<const float4*>(sgrad);

            float acc[7] = {0, 0, 0, 0, 0, 0, 0};
            for (int j = tid; j < WIDTH; j += 256) {
                float4 w0 = Wr[j * 2];
                float4 w1 = Wr[j * 2 + 1];
                float4 g0 = gg[j * 2];
                float4 g1 = gg[j * 2 + 1];
                acc[0] = fmaf(w0.y, g0.y, acc[0]);
                acc[1] = fmaf(w0.z, g0.z, acc[1]);
                acc[2] = fmaf(w0.w, g0.w, acc[2]);
                acc[3] = fmaf(w1.x, g1.x, acc[3]);
                acc[4] = fmaf(w1.y, g1.y, acc[4]);
                acc[5] = fmaf(w1.z, g1.z, acc[5]);
                acc[6] = fmaf(w1.w, g1.w, acc[6]);
            }
            float (*red)[7] = reinterpret_cast<float (*)[7]>(sh);
#pragma unroll
            for (int a = 0; a < 7; ++a)
#pragma unroll
                for (int off = 16; off; off >>= 1)
                    acc[a] += __shfl_down_sync(0xffffffffu, acc[a], off);
            if ((tid & 31) == 0) {
                int w = tid >> 5;
#pragma unroll
                for (int a = 0; a < 7; ++a) red[w][a] = acc[a];
            }
            __syncthreads();
            if (tid < 7) {
                float s = 0.f;
#pragma unroll
                for (int w = 0; w < 8; ++w) s += red[w][tid];
                g_contrib[(size_t)i * 8 + tid] = s;
            }
        }
    } else {
        // ---- saog: pure dual copy, sector-aligned stores (quad idx = 3+4q).
        // Streaming loads (__ldcs) so this no-reuse stream doesn't evict the
        // W lines the two reduction roles dedup on in L2.
        const int sid = bx - bx / 3 - 1;   // 0..4607
        const int q = sid * 256 + tid;
        if (q >= NQ_SAOG) return;
        const int idx = 3 + 4 * q;

        const float4* sa4 = reinterpret_cast<const float4*>(sa_in);
        const float4* og4 = reinterpret_cast<const float4*>(og_in);
        float4 sA = __ldcs(sa4 + q), sB = __ldcs(sa4 + q + 1);
        float4 oA = __ldcs(og4 + q), oB = __ldcs(og4 + q + 1);

        *reinterpret_cast<float4*>(&out[OFF_SA + idx]) =
            make_float4(sA.w, sB.x, sB.y, sB.z);
        *reinterpret_cast<float4*>(&out[OFF_OG + idx]) =
            make_float4(oA.w, oB.x, oB.y, oB.z);

        if (q == 0) {
#pragma unroll
            for (int e = 0; e < 3; ++e) {
                out[OFF_SA + e] = sa_in[e];
                out[OFF_OG + e] = og_in[e];
            }
        }
        if (q == NQ_SAOG - 1) {
            out[OFF_SA + N_SAOG - 1] = sa_in[N_SAOG - 1];
            out[OFF_OG + N_SAOG - 1] = og_in[N_SAOG - 1];
        }
    }
}

// ---------------------------------------------------------------------------
// finalize — state/owg, output dot, full sg logic, m / m-shift / aprev,
// PLUS the sa/og time-slice overwrite (k_main copied stale values there).
// tia(a) = time + 2a - 14 (mod 242); tia==time only at a=7, (tia±1)!=time
// for all a -> all sa/og reads at a<7 hit the ORIGINAL arrays; at a=7 the
// only aliased read is this thread's own fresh state value.
// ---------------------------------------------------------------------------
__global__ void k_finalize(float* __restrict__ out,
                           const float* __restrict__ x,
                           const float* __restrict__ ow,
                           const float* __restrict__ sa_in,
                           const float* __restrict__ og_in,
                           const int* __restrict__ time_p) {
    const int k = blockIdx.x * blockDim.x + threadIdx.x;   // 0..WD-1
    const int w = k >> 3, a = k & 7;
    const int time = *time_p;

    float h = 0.f;
#pragma unroll
    for (int c = 0; c < NSPLIT; ++c) h += g_hpart[c][k];
    float s = fmaxf(h, 0.f);

    size_t o = (size_t)w * DP1 + a + 1;
    out[OFF_STATE + o] = s;
    out[OFF_OWG + o]   = s;
    // time-slice fixup for the copies
    out[OFF_SA + o * TMOD + time] = s;
    out[OFF_OG + o * TMOD + time] = ow[o];
    float v = ow[o] * s;
    if (a == 0) {
        float xv = x[w];
        size_t o0 = (size_t)w * DP1;
        out[OFF_STATE + o0] = xv;
        out[OFF_OWG   + o0] = xv;
        out[OFF_SA + o0 * TMOD + time] = xv;
        out[OFF_OG + o0 * TMOD + time] = ow[o0];
        v = fmaf(ow[o0], xv, v);
    }

    const int tia = posmod(time - 2 * DEPTH + 2 * (a + 1), TMOD);
    float sgv, rg, aprev;
    if (a < DEPTH - 1) {
        int t1 = (tia + 1) % TMOD;
        float rmv = sa_in[((size_t)w * DP1 + a + 2) * TMOD + t1];
        sgv = fmaf(rmv > 0.f ? 1.f : 0.f, g_contrib[k],
                   og_in[((size_t)w * DP1 + a + 1) * TMOD + tia]);
        rg = (sa_in[((size_t)w * DP1 + a + 1) * TMOD + tia] > 0.f) ? 1.f : 0.f;
        aprev = sa_in[((size_t)w * DP1 + a) * TMOD + posmod(tia - 1, TMOD)];
    } else {
        sgv = ow[(size_t)w * DP1 + DEPTH];
        rg = (s > 0.f) ? 1.f : 0.f;
        aprev = sa_in[((size_t)w * DP1 + DEPTH - 1) * TMOD + posmod(time - 1, TMOD)];
    }
    out[OFF_SG + k] = sgv;
    float mval = sgv * rg;
    g_m[k] = mval;
    if (k >= 3) g_mshift[k - 3] = mval;
    g_aprev[k] = aprev;

    __shared__ float red[8];
#pragma unroll
    for (int off = 16; off; off >>= 1)
        v += __shfl_down_sync(0xffffffffu, v, off);
    if ((threadIdx.x & 31) == 0) red[threadIdx.x >> 5] = v;
    __syncthreads();
    if (threadIdx.x == 0) {
        float t = 0.f;
#pragma unroll
        for (int i = 0; i < 8; ++i) t += red[i];
        atomicAdd(&g_out_acc, t);
    }
}

// ---------------------------------------------------------------------------
// grad: gradients[i,j,a] = aprev[i,a] * m[j,a]; block-per-row (round-8
// measured-best scheme), sector-aligned via mshift.
// ---------------------------------------------------------------------------
__global__ void k_grad(float* __restrict__ out) {
    const int i = blockIdx.x;
    const int tid = threadIdx.x;
    if (i == 0 && tid == 0) out[OFF_OUT] = g_out_acc;

    const float* ap = g_aprev + (size_t)i * 8;
    const float4 apv = (tid & 1)
        ? make_float4(__ldg(ap + 7), __ldg(ap + 0), __ldg(ap + 1), __ldg(ap + 2))
        : make_float4(__ldg(ap + 3), __ldg(ap + 4), __ldg(ap + 5), __ldg(ap + 6));

    float* dst = out + OFF_GRAD + (size_t)i * WD;
    const float4* ms4 = reinterpret_cast<const float4*>(g_mshift);

    for (int q = tid; q < NQ_GROW; q += 256) {
        float4 mv = ms4[q];
        *reinterpret_cast<float4*>(dst + 3 + 4 * q) =
            make_float4(apv.x * mv.x, apv.y * mv.y,
                        apv.z * mv.z, apv.w * mv.w);
    }
    if (tid == 0) {
        dst[0] = __ldg(ap + 0) * g_m[0];
        dst[1] = __ldg(ap + 1) * g_m[1];
        dst[2] = __ldg(ap + 2) * g_m[2];
    } else if (tid == 1) {
        dst[WD - 1] = __ldg(ap + 7) * g_m[WD - 1];
    }
}

// ---------------------------------------------------------------------------
extern "C" void kernel_launch(void* const* d_in, const int* in_sizes, int n_in,
                              void* d_out, int out_size) {
    const float* x    = (const float*)d_in[0];
    const float* W    = (const float*)d_in[1];
    const float* ow   = (const float*)d_in[2];
    const float* st   = (const float*)d_in[3];
    const float* sa   = (const float*)d_in[4];
    const float* sgr  = (const float*)d_in[5];
    const float* og   = (const float*)d_in[6];
    const int*   tim  = (const int*)d_in[7];
    float* out = (float*)d_out;

    k_main<<<MAIN_BLK, 256>>>(W, st, sgr, out, sa, og);
    k_finalize<<<WD / 256, 256>>>(out, x, ow, sa, og, tim);
    k_grad<<<WIDTH, 256>>>(out);
}